// round 7
// baseline (speedup 1.0000x reference)
#include <cuda_runtime.h>
#include <math.h>
#include <stdint.h>

#define TT 2048
#define BB 64
#define KIN 256
#define HH 256

typedef unsigned long long ull;

// Scratch for precomputed input projection xp[t][b][h] (134 MB device global).
__device__ float g_xp[(size_t)TT * BB * HH];

// ---------------------------------------------------------------------------
// f32x2 helpers (Blackwell packed fp32 pipe)
// ---------------------------------------------------------------------------
__device__ __forceinline__ ull ffma2(ull a, ull b, ull c) {
    ull d;
    asm("fma.rn.f32x2 %0, %1, %2, %3;" : "=l"(d) : "l"(a), "l"(b), "l"(c));
    return d;
}
__device__ __forceinline__ ull fdup2(float a) {
    ull d; unsigned u = __float_as_uint(a);
    asm("mov.b64 %0, {%1, %2};" : "=l"(d) : "r"(u), "r"(u));
    return d;
}
__device__ __forceinline__ float2 funpack2(ull a) {
    unsigned lo, hi;
    asm("mov.b64 {%0, %1}, %2;" : "=r"(lo), "=r"(hi) : "l"(a));
    return make_float2(__uint_as_float(lo), __uint_as_float(hi));
}

// ---------------------------------------------------------------------------
// Kernel 1: xp[m][n] = x[m][:] . W_ih[n][:] + b_ih[n] + b_hh[n]   (f32x2 GEMM)
// 128x128 tile, BK=16, 256 threads, per-thread 8x8 via packed f32x2.
// ---------------------------------------------------------------------------
__global__ __launch_bounds__(256, 2) void xp_gemm_kernel(
    const float* __restrict__ x,
    const float* __restrict__ Wih,
    const float* __restrict__ b_ih,
    const float* __restrict__ b_hh)
{
    __shared__ __align__(16) float As[16][132];   // [k][m]
    __shared__ __align__(16) float Bs[16][132];   // [k][n]

    const int tid = threadIdx.x;
    const int m0 = blockIdx.x * 128;
    const int n0 = blockIdx.y * 128;
    const int ty = tid >> 4;
    const int tx = tid & 15;

    ull acc[8][4];   // [row i][col-pair p]
#pragma unroll
    for (int i = 0; i < 8; i++)
#pragma unroll
        for (int p = 0; p < 4; p++) acc[i][p] = 0ull;

    for (int kt = 0; kt < KIN; kt += 16) {
#pragma unroll
        for (int l = 0; l < 2; l++) {
            int id  = tid + l * 256;
            int row = id >> 2;
            int c4  = (id & 3) * 4;
            float4 av = *(const float4*)(x   + (size_t)(m0 + row) * KIN + kt + c4);
            As[c4 + 0][row] = av.x; As[c4 + 1][row] = av.y;
            As[c4 + 2][row] = av.z; As[c4 + 3][row] = av.w;
            float4 bv = *(const float4*)(Wih + (size_t)(n0 + row) * KIN + kt + c4);
            Bs[c4 + 0][row] = bv.x; Bs[c4 + 1][row] = bv.y;
            Bs[c4 + 2][row] = bv.z; Bs[c4 + 3][row] = bv.w;
        }
        __syncthreads();

#pragma unroll
        for (int k = 0; k < 16; k++) {
            float4 a03 = *(const float4*)&As[k][ty * 8];
            float4 a47 = *(const float4*)&As[k][ty * 8 + 4];
            ulonglong2 bq0 = *(const ulonglong2*)&Bs[k][tx * 8];
            ulonglong2 bq1 = *(const ulonglong2*)&Bs[k][tx * 8 + 4];
            ull bp[4] = { bq0.x, bq0.y, bq1.x, bq1.y };
            float av[8] = { a03.x, a03.y, a03.z, a03.w, a47.x, a47.y, a47.z, a47.w };
#pragma unroll
            for (int i = 0; i < 8; i++) {
                ull ad = fdup2(av[i]);
#pragma unroll
                for (int p = 0; p < 4; p++)
                    acc[i][p] = ffma2(ad, bp[p], acc[i][p]);
            }
        }
        __syncthreads();
    }

    float bb[8];
#pragma unroll
    for (int j = 0; j < 8; j++) {
        int n = n0 + tx * 8 + j;
        bb[j] = b_ih[n] + b_hh[n];
    }
#pragma unroll
    for (int i = 0; i < 8; i++) {
        float* dst = g_xp + (size_t)(m0 + ty * 8 + i) * HH + n0 + tx * 8;
        float2 c0 = funpack2(acc[i][0]);
        float2 c1 = funpack2(acc[i][1]);
        float2 c2 = funpack2(acc[i][2]);
        float2 c3 = funpack2(acc[i][3]);
        float4 v0 = make_float4(c0.x + bb[0], c0.y + bb[1], c1.x + bb[2], c1.y + bb[3]);
        float4 v1 = make_float4(c2.x + bb[4], c2.y + bb[5], c3.x + bb[6], c3.y + bb[7]);
        *(float4*)dst       = v0;
        *(float4*)(dst + 4) = v1;
    }
}

// ---------------------------------------------------------------------------
// Kernel 2: serial recurrence. ONE CTA per batch element (64 CTAs), 256 thr.
//   No cross-CTA communication; sync is plain __syncthreads().
//   Thread (g = tid>>2, c = tid&3): rows 4g..4g+3, K-chunk [64c, 64c+64).
//   W per thread = 256 floats: 208 in registers (104 ull), 48 in SMEM
//   (12 float4, lane-strided conflict-free layout).
//   Per step: 128 FFMA2, 2-round shfl.bfly reduce over c, tanh by c==0,
//   float4 h/out stores, xp prefetched one step ahead.
// ---------------------------------------------------------------------------
__global__ __launch_bounds__(256, 1) void rnn_scan_kernel(
    const float* __restrict__ Whh,
    float* __restrict__ out)
{
    extern __shared__ float smem[];
    float4* Wsm  = (float4*)smem;            // 12 * 256 float4 = 48 KB
    float*  hsm  = smem + 12 * 256 * 4;      // 256 floats

    const int tid = threadIdx.x;
    const int b   = blockIdx.x;
    const int c   = tid & 3;                 // K-chunk selector
    const int g   = tid >> 2;                // row group: rows 4g..4g+3
    const int k0  = 64 * c;

    // Stage W: per row 64 floats -> 52 regs (26 ull) + 12 smem (3 float4).
    ull wr[4][26];
#pragma unroll
    for (int r = 0; r < 4; r++) {
        const float* rowp = Whh + (size_t)(4 * g + r) * HH + k0;
        const ull* p = (const ull*)rowp;
#pragma unroll
        for (int i = 0; i < 26; i++) wr[r][i] = p[i];
        const float4* src = (const float4*)(rowp + 52);   // 52*4=208 B, 16B aligned
#pragma unroll
        for (int q = 0; q < 3; q++) Wsm[(r * 3 + q) * 256 + tid] = src[q];
    }
    hsm[tid] = 0.0f;                          // h_{-1} = 0
    __syncthreads();

    const size_t tstride = (size_t)BB * HH;
    const float* xpp  = g_xp + (size_t)b * HH + 4 * g;
    float*       outp = out  + (size_t)b * HH + 4 * g;

    float4 xv = make_float4(0.f, 0.f, 0.f, 0.f);
    if (c == 0) xv = *(const float4*)xpp;     // xp for t = 0

    const ulonglong2* Wsm2 = (const ulonglong2*)Wsm;

    for (int t = 0; t < TT; t++) {
        const ulonglong2* h2 = (const ulonglong2*)(hsm + k0);
        ull a0 = 0ull, a1 = 0ull, a2 = 0ull, a3 = 0ull;

        // 13 register chunks of 4 h-floats each (52 floats)
#pragma unroll
        for (int i = 0; i < 13; i++) {
            ulonglong2 hq = h2[i];
            a0 = ffma2(wr[0][2 * i], hq.x, a0);
            a1 = ffma2(wr[1][2 * i], hq.x, a1);
            a2 = ffma2(wr[2][2 * i], hq.x, a2);
            a3 = ffma2(wr[3][2 * i], hq.x, a3);
            a0 = ffma2(wr[0][2 * i + 1], hq.y, a0);
            a1 = ffma2(wr[1][2 * i + 1], hq.y, a1);
            a2 = ffma2(wr[2][2 * i + 1], hq.y, a2);
            a3 = ffma2(wr[3][2 * i + 1], hq.y, a3);
        }
        // 3 smem chunks (h floats 52..63)
#pragma unroll
        for (int q = 0; q < 3; q++) {
            ulonglong2 hq = h2[13 + q];
            ulonglong2 w0 = Wsm2[(0 * 3 + q) * 256 + tid];
            ulonglong2 w1 = Wsm2[(1 * 3 + q) * 256 + tid];
            ulonglong2 w2 = Wsm2[(2 * 3 + q) * 256 + tid];
            ulonglong2 w3 = Wsm2[(3 * 3 + q) * 256 + tid];
            a0 = ffma2(w0.x, hq.x, a0);
            a1 = ffma2(w1.x, hq.x, a1);
            a2 = ffma2(w2.x, hq.x, a2);
            a3 = ffma2(w3.x, hq.x, a3);
            a0 = ffma2(w0.y, hq.y, a0);
            a1 = ffma2(w1.y, hq.y, a1);
            a2 = ffma2(w2.y, hq.y, a2);
            a3 = ffma2(w3.y, hq.y, a3);
        }

        float2 u0 = funpack2(a0), u1 = funpack2(a1);
        float2 u2 = funpack2(a2), u3 = funpack2(a3);
        float s0 = u0.x + u0.y, s1 = u1.x + u1.y;
        float s2 = u2.x + u2.y, s3 = u3.x + u3.y;
#pragma unroll
        for (int m = 1; m < 4; m <<= 1) {
            s0 += __shfl_xor_sync(0xffffffffu, s0, m);
            s1 += __shfl_xor_sync(0xffffffffu, s1, m);
            s2 += __shfl_xor_sync(0xffffffffu, s2, m);
            s3 += __shfl_xor_sync(0xffffffffu, s3, m);
        }

        __syncthreads();   // all hsm reads of step t complete
        if (c == 0) {
            float4 hn = make_float4(tanhf(s0 + xv.x), tanhf(s1 + xv.y),
                                    tanhf(s2 + xv.z), tanhf(s3 + xv.w));
            *(float4*)&hsm[4 * g] = hn;
            *(float4*)(outp + (size_t)t * tstride) = hn;
            if (t + 1 < TT)
                xv = *(const float4*)(xpp + (size_t)(t + 1) * tstride);
        }
        __syncthreads();   // new h visible to all
    }
}

// ---------------------------------------------------------------------------
// Launch
// ---------------------------------------------------------------------------
extern "C" void kernel_launch(void* const* d_in, const int* in_sizes, int n_in,
                              void* d_out, int out_size)
{
    const float* x    = (const float*)d_in[0];
    const float* Wih  = (const float*)d_in[1];
    const float* Whh  = (const float*)d_in[2];
    const float* b_ih = (const float*)d_in[3];
    const float* b_hh = (const float*)d_in[4];
    float* out = (float*)d_out;

    dim3 g1((TT * BB) / 128, HH / 128);
    xp_gemm_kernel<<<g1, 256>>>(x, Wih, b_ih, b_hh);

    const int smem_bytes = (12 * 256 * 4 + 256) * (int)sizeof(float);  // 50176
    cudaFuncSetAttribute(rnn_scan_kernel,
                         cudaFuncAttributeMaxDynamicSharedMemorySize, smem_bytes);
    rnn_scan_kernel<<<BB, 256, smem_bytes>>>(Whh, out);
}

// round 8
// speedup vs baseline: 1.9092x; 1.9092x over previous
#include <cuda_runtime.h>
#include <math.h>
#include <stdint.h>

#define TT 2048
#define BB 64
#define KIN 256
#define HH 256

typedef unsigned long long ull;

// Scratch for precomputed input projection xp[t][b][h] (134 MB device global).
__device__ float g_xp[(size_t)TT * BB * HH];

// ---------------------------------------------------------------------------
// f32x2 helpers (Blackwell packed fp32 pipe)
// ---------------------------------------------------------------------------
__device__ __forceinline__ ull ffma2(ull a, ull b, ull c) {
    ull d;
    asm("fma.rn.f32x2 %0, %1, %2, %3;" : "=l"(d) : "l"(a), "l"(b), "l"(c));
    return d;
}
__device__ __forceinline__ ull fdup2(float a) {
    ull d; unsigned u = __float_as_uint(a);
    asm("mov.b64 %0, {%1, %2};" : "=l"(d) : "r"(u), "r"(u));
    return d;
}
__device__ __forceinline__ ull fpack2(float a, float b) {
    ull d;
    asm("mov.b64 %0, {%1, %2};" : "=l"(d)
        : "r"(__float_as_uint(a)), "r"(__float_as_uint(b)));
    return d;
}
__device__ __forceinline__ float2 funpack2(ull a) {
    unsigned lo, hi;
    asm("mov.b64 {%0, %1}, %2;" : "=r"(lo), "=r"(hi) : "l"(a));
    return make_float2(__uint_as_float(lo), __uint_as_float(hi));
}
__device__ __forceinline__ uint32_t smem_u32(const void* p) {
    uint32_t a;
    asm("{ .reg .u64 t; cvta.to.shared.u64 t, %1; cvt.u32.u64 %0, t; }"
        : "=r"(a) : "l"(p));
    return a;
}
__device__ __forceinline__ uint32_t mapa_peer(uint32_t local, uint32_t peer) {
    uint32_t r;
    asm("mapa.shared::cluster.u32 %0, %1, %2;" : "=r"(r) : "r"(local), "r"(peer));
    return r;
}
__device__ __forceinline__ void st_async_b64(uint32_t raddr, ull v, uint32_t rbar) {
    asm volatile(
        "st.async.shared::cluster.mbarrier::complete_tx::bytes.b64 [%0], %1, [%2];"
        :: "r"(raddr), "l"(v), "r"(rbar) : "memory");
}
__device__ __forceinline__ void mbar_init(uint32_t addr, uint32_t cnt) {
    asm volatile("mbarrier.init.shared.b64 [%0], %1;" :: "r"(addr), "r"(cnt) : "memory");
}
__device__ __forceinline__ void mbar_expect_tx(uint32_t addr, uint32_t bytes) {
    asm volatile("mbarrier.arrive.expect_tx.shared.b64 _, [%0], %1;"
                 :: "r"(addr), "r"(bytes) : "memory");
}
__device__ __forceinline__ void mbar_wait_parity(uint32_t addr, uint32_t parity) {
    asm volatile(
        "{\n\t"
        ".reg .pred P;\n\t"
        "WL_%=:\n\t"
        "mbarrier.try_wait.parity.acquire.cluster.shared::cta.b64 P, [%0], %1, 0x989680;\n\t"
        "@!P bra WL_%=;\n\t"
        "}" :: "r"(addr), "r"(parity) : "memory");
}
#define CLUSTER_SYNC_() do { \
    asm volatile("barrier.cluster.arrive.aligned;" ::: "memory"); \
    asm volatile("barrier.cluster.wait.aligned;" ::: "memory"); \
} while (0)

// ---------------------------------------------------------------------------
// Kernel 1: xp[m][n] = x[m][:] . W_ih[n][:] + b_ih[n] + b_hh[n]   (f32x2 GEMM)
// (unchanged: passed with rel_err 1.8e-7)
// ---------------------------------------------------------------------------
__global__ __launch_bounds__(256, 2) void xp_gemm_kernel(
    const float* __restrict__ x,
    const float* __restrict__ Wih,
    const float* __restrict__ b_ih,
    const float* __restrict__ b_hh)
{
    __shared__ __align__(16) float As[16][132];
    __shared__ __align__(16) float Bs[16][132];

    const int tid = threadIdx.x;
    const int m0 = blockIdx.x * 128;
    const int n0 = blockIdx.y * 128;
    const int ty = tid >> 4;
    const int tx = tid & 15;

    ull acc[8][4];
#pragma unroll
    for (int i = 0; i < 8; i++)
#pragma unroll
        for (int p = 0; p < 4; p++) acc[i][p] = 0ull;

    for (int kt = 0; kt < KIN; kt += 16) {
#pragma unroll
        for (int l = 0; l < 2; l++) {
            int id  = tid + l * 256;
            int row = id >> 2;
            int c4  = (id & 3) * 4;
            float4 av = *(const float4*)(x   + (size_t)(m0 + row) * KIN + kt + c4);
            As[c4 + 0][row] = av.x; As[c4 + 1][row] = av.y;
            As[c4 + 2][row] = av.z; As[c4 + 3][row] = av.w;
            float4 bv = *(const float4*)(Wih + (size_t)(n0 + row) * KIN + kt + c4);
            Bs[c4 + 0][row] = bv.x; Bs[c4 + 1][row] = bv.y;
            Bs[c4 + 2][row] = bv.z; Bs[c4 + 3][row] = bv.w;
        }
        __syncthreads();

#pragma unroll
        for (int k = 0; k < 16; k++) {
            float4 a03 = *(const float4*)&As[k][ty * 8];
            float4 a47 = *(const float4*)&As[k][ty * 8 + 4];
            ulonglong2 bq0 = *(const ulonglong2*)&Bs[k][tx * 8];
            ulonglong2 bq1 = *(const ulonglong2*)&Bs[k][tx * 8 + 4];
            ull bp[4] = { bq0.x, bq0.y, bq1.x, bq1.y };
            float av[8] = { a03.x, a03.y, a03.z, a03.w, a47.x, a47.y, a47.z, a47.w };
#pragma unroll
            for (int i = 0; i < 8; i++) {
                ull ad = fdup2(av[i]);
#pragma unroll
                for (int p = 0; p < 4; p++)
                    acc[i][p] = ffma2(ad, bp[p], acc[i][p]);
            }
        }
        __syncthreads();
    }

    float bb[8];
#pragma unroll
    for (int j = 0; j < 8; j++) {
        int n = n0 + tx * 8 + j;
        bb[j] = b_ih[n] + b_hh[n];
    }
#pragma unroll
    for (int i = 0; i < 8; i++) {
        float* dst = g_xp + (size_t)(m0 + ty * 8 + i) * HH + n0 + tx * 8;
        float2 c0 = funpack2(acc[i][0]);
        float2 c1 = funpack2(acc[i][1]);
        float2 c2 = funpack2(acc[i][2]);
        float2 c3 = funpack2(acc[i][3]);
        float4 v0 = make_float4(c0.x + bb[0], c0.y + bb[1], c1.x + bb[2], c1.y + bb[3]);
        float4 v1 = make_float4(c2.x + bb[4], c2.y + bb[5], c3.x + bb[6], c3.y + bb[7]);
        *(float4*)dst       = v0;
        *(float4*)(dst + 4) = v1;
    }
}

// ---------------------------------------------------------------------------
// Kernel 2: serial recurrence. Cluster of 2 CTAs per batch (grid 128).
// CTA rank r owns output rows [128r, 128r+128). 512 threads:
//   thread -> jg = tid>>3 (local rows 2jg, 2jg+1), c = tid&7 (K in [32c,32c+32))
//   W fully register-resident (32 ull). 8-lane shfl reduce. h buffers are
//   PADDED (36-float chunk stride) so the 8 per-warp chunk reads are
//   conflict-free. Cross-CTA h exchange: st.async.b64 + TWO mbarriers
//   alternated by t&1 (each flips every 2 steps -> parity (t>>1)&1),
//   eliminating the adjacent-phase tx-mixing race of round 5.
// ---------------------------------------------------------------------------
#define HPAD 36                      // padded chunk stride (floats)
#define HBUF (8 * HPAD)              // 288 floats per h buffer

__global__ __launch_bounds__(512, 1) __cluster_dims__(2, 1, 1)
void rnn_scan_kernel(const float* __restrict__ Whh, float* __restrict__ out)
{
    __shared__ __align__(16) float hsm[2][HBUF];
    __shared__ __align__(8)  ull   mbars[2];

    const int tid = threadIdx.x;
    const unsigned rank = blockIdx.x & 1u;
    const int batch = blockIdx.x >> 1;
    const int c  = tid & 7;
    const int jg = tid >> 3;
    const int j0 = (int)rank * 128 + 2 * jg;       // global output row (even)
    const unsigned wofs = (unsigned)(HPAD * (j0 >> 5) + (j0 & 31));  // padded slot

    const uint32_t mb0 = smem_u32(&mbars[0]);
    const uint32_t mb1 = smem_u32(&mbars[1]);
    const uint32_t hsm_addr = smem_u32(&hsm[0][0]);
    const uint32_t peer = rank ^ 1u;
    const uint32_t peer_mb0 = mapa_peer(mb0, peer);
    const uint32_t peer_mb1 = mapa_peer(mb1, peer);
    const uint32_t peer_hsm = mapa_peer(hsm_addr, peer);

    // Register-resident W: rows j0, j0+1, K in [32c, 32c+32) as f32x2 pairs.
    ull w0[16], w1[16];
    {
        const ull* w0p = (const ull*)(Whh + (size_t)j0 * HH + 32 * c);
        const ull* w1p = (const ull*)(Whh + (size_t)(j0 + 1) * HH + 32 * c);
#pragma unroll
        for (int i = 0; i < 16; i++) { w0[i] = w0p[i]; w1[i] = w1p[i]; }
    }

    if (tid < HBUF) hsm[0][tid] = 0.0f;            // h_{-1} = 0 (buffer 0)
    if (tid == 0) { mbar_init(mb0, 1); mbar_init(mb1, 1); }
    __syncthreads();
    CLUSTER_SYNC_();                                // peer mbars visible

    const size_t tstride = (size_t)BB * HH;
    const float* xpp  = g_xp + (size_t)batch * HH + j0;
    float*       outp = out  + (size_t)batch * HH + j0;

    float2 xv = make_float2(0.f, 0.f);
    if (c == 0) xv = *(const float2*)xpp;           // xp for t = 0

    for (int t = 0; t < TT; t++) {
        const unsigned par = (unsigned)t & 1u;
        const uint32_t mbar      = par ? mb1 : mb0;
        const uint32_t peer_mbar = par ? peer_mb1 : peer_mb0;
        const unsigned phase     = ((unsigned)t >> 1) & 1u;  // mbar flips every 2 t

        if (tid == 0) mbar_expect_tx(mbar, 512);    // 64 peer lanes x 8 B

        // Partial dot products over K-chunk [32c, 32c+32) for rows j0, j0+1.
        const ulonglong2* hp = (const ulonglong2*)&hsm[par][HPAD * c];
        ull a0 = 0ull, a1 = 0ull;
#pragma unroll
        for (int i = 0; i < 8; i++) {
            ulonglong2 hq = hp[i];
            a0 = ffma2(w0[2 * i],     hq.x, a0);
            a1 = ffma2(w1[2 * i],     hq.x, a1);
            a0 = ffma2(w0[2 * i + 1], hq.y, a0);
            a1 = ffma2(w1[2 * i + 1], hq.y, a1);
        }
        float2 u0 = funpack2(a0), u1 = funpack2(a1);
        float s0 = u0.x + u0.y;
        float s1 = u1.x + u1.y;
#pragma unroll
        for (int m = 1; m < 8; m <<= 1) {
            s0 += __shfl_xor_sync(0xffffffffu, s0, m);
            s1 += __shfl_xor_sync(0xffffffffu, s1, m);
        }

        if (c == 0) {
            float h0 = tanhf(s0 + xv.x);
            float h1 = tanhf(s1 + xv.y);
            const unsigned nb = par ^ 1u;
            // local store into next buffer (own half), padded layout
            *(float2*)&hsm[nb][wofs] = make_float2(h0, h1);
            // remote store into peer's next buffer + tx on peer's mbar[par]
            uint32_t raddr = peer_hsm + (nb * (unsigned)HBUF + wofs) * 4u;
            st_async_b64(raddr, fpack2(h0, h1), peer_mbar);
            // output (unpadded global layout)
            *(float2*)(outp + (size_t)t * tstride) = make_float2(h0, h1);
            // prefetch next step's xp
            if (t + 1 < TT)
                xv = *(const float2*)(xpp + (size_t)(t + 1) * tstride);
        }

        // Wait for peer's 512 B of step t, then publish local writes CTA-wide.
        mbar_wait_parity(mbar, phase);
        __syncthreads();
    }
    CLUSTER_SYNC_();
}

// ---------------------------------------------------------------------------
// Launch
// ---------------------------------------------------------------------------
extern "C" void kernel_launch(void* const* d_in, const int* in_sizes, int n_in,
                              void* d_out, int out_size)
{
    const float* x    = (const float*)d_in[0];
    const float* Wih  = (const float*)d_in[1];
    const float* Whh  = (const float*)d_in[2];
    const float* b_ih = (const float*)d_in[3];
    const float* b_hh = (const float*)d_in[4];
    float* out = (float*)d_out;

    dim3 g1((TT * BB) / 128, HH / 128);
    xp_gemm_kernel<<<g1, 256>>>(x, Wih, b_ih, b_hh);

    rnn_scan_kernel<<<2 * BB, 512>>>(Whh, out);
}